// round 5
// baseline (speedup 1.0000x reference)
#include <cuda_runtime.h>
#include <cstdint>

// CRF NLL, linear-domain scaled forward. B=256, L=512, T=32 (START=30, STOP=31).
// One warp per batch (one block per batch, WPB=1), thread j = tag j.
//   alpha'_j = g_j * s * sum_i E[i][j] * alpha_i
//   E = exp(trans) in registers (packed f32x2 column per thread),
//   g_j = exp(feats[l,j]) computed in the LDS latency shadow,
//   s = 2^{-k} exact rescale from exponent field of shfl'd alpha (off-chain).
// Per-step __syncwarp removed: loop is divergence-free, so same-warp STS->LDS
// in-order MIO wavefront ordering guarantees visibility; volatile asm pins
// compiler order. Gold path computed after the scan. Reduction fused.

static constexpr int Bn = 256;
static constexpr int Ln = 512;
static constexpr int Tn = 32;
static constexpr int T_START = 30;
static constexpr int T_STOP  = 31;
static constexpr int NBLK = Bn;          // one warp per block per batch

#define FULLMASK 0xffffffffu
#define LOG2E_F 1.4426950408889634f
#define LN2_F   0.6931471805599453f

typedef unsigned long long ull;

__device__ float g_res[Bn];
__device__ int g_cnt = 0;

__device__ __forceinline__ float ex2f_(float x) {
    float y; asm("ex2.approx.f32 %0, %1;" : "=f"(y) : "f"(x)); return y;
}
__device__ __forceinline__ float lg2f_(float x) {
    float y; asm("lg2.approx.f32 %0, %1;" : "=f"(y) : "f"(x)); return y;
}
__device__ __forceinline__ ull fma2_(ull a, ull b, ull c) {
    ull d; asm("fma.rn.f32x2 %0, %1, %2, %3;" : "=l"(d) : "l"(a), "l"(b), "l"(c));
    return d;
}
__device__ __forceinline__ ull mul2_(ull a, ull b) {
    ull d; asm("mul.rn.f32x2 %0, %1, %2;" : "=l"(d) : "l"(a), "l"(b));
    return d;
}
__device__ __forceinline__ ull add2_(ull a, ull b) {
    ull d; asm("add.rn.f32x2 %0, %1, %2;" : "=l"(d) : "l"(a), "l"(b));
    return d;
}
__device__ __forceinline__ ull pack2_(float lo, float hi) {
    ull d;
    asm("mov.b64 %0, {%1, %2};" : "=l"(d)
        : "r"(__float_as_uint(lo)), "r"(__float_as_uint(hi)));
    return d;
}
__device__ __forceinline__ void unpack2_(ull v, float& lo, float& hi) {
    unsigned a, b;
    asm("mov.b64 {%0, %1}, %2;" : "=r"(a), "=r"(b) : "l"(v));
    lo = __uint_as_float(a); hi = __uint_as_float(b);
}
// LDS.128 as two packed 64-bit regs (no repack MOVs). volatile: pinned order.
__device__ __forceinline__ void lds128_(ull& a, ull& b, unsigned addr) {
    asm volatile("ld.shared.v2.b64 {%0, %1}, [%2];"
                 : "=l"(a), "=l"(b) : "r"(addr));
}
__device__ __forceinline__ void sts32_(unsigned addr, float v) {
    asm volatile("st.shared.b32 [%0], %1;" :: "r"(addr), "f"(v) : "memory");
}

__global__ void __launch_bounds__(32, 1)
crf_kernel(const float* __restrict__ feats,
           const void* __restrict__ maskp,
           const int* __restrict__ tags,
           const float* __restrict__ trans,
           float* __restrict__ out) {
    __shared__ __align__(16) float sm_e[2][Tn];

    const int lane = threadIdx.x & 31;
    const int b = blockIdx.x;

    const float* __restrict__ fb = feats + (size_t)b * (Ln * Tn);
    const int* __restrict__ tb = tags + (size_t)b * Ln;

    // smem addresses (shared state space)
    const unsigned sb0 = (unsigned)__cvta_generic_to_shared(&sm_e[0][0]);
    const unsigned sb1 = sb0 + Tn * 4;
    const unsigned stAddr0 = sb0 + lane * 4;
    const unsigned stAddr1 = sb1 + lane * 4;

    // ---- sequence length (mask = contiguous true-prefix; dtype detected) ----
    const unsigned w0 = ((const unsigned*)maskp)[0];  // mask[0,0] is true
    int cnt = 0;
    if (w0 == 1u) {                       // bool as int32
        const int* mb = (const int*)maskp + (size_t)b * Ln;
        #pragma unroll 4
        for (int l = lane; l < Ln; l += 32) cnt += (mb[l] != 0);
    } else if (w0 == 0x3F800000u) {       // bool as float32
        const float* mb = (const float*)maskp + (size_t)b * Ln;
        #pragma unroll 4
        for (int l = lane; l < Ln; l += 32) cnt += (mb[l] != 0.0f);
    } else {                              // bool as uint8
        const unsigned char* mb = (const unsigned char*)maskp + (size_t)b * Ln;
        #pragma unroll 4
        for (int l = lane; l < Ln; l += 32) cnt += (mb[l] != 0);
    }
    const int len = __reduce_add_sync(FULLMASK, cnt);

    // ---- E column for tag j = lane: E2[i] = {exp(trans[2i][j]), exp(trans[2i+1][j])} ----
    ull E2[Tn / 2];
    #pragma unroll
    for (int i = 0; i < Tn / 2; i++) {
        float e0 = ex2f_(trans[(2 * i) * Tn + lane] * LOG2E_F);
        float e1 = ex2f_(trans[(2 * i + 1) * Tn + lane] * LOG2E_F);
        E2[i] = pack2_(e0, e1);
    }

    // ---- init: alpha_j = exp(feats[0,j] + trans[START,j]), K = 0 ----
    float A = ex2f_((fb[lane] + trans[T_START * Tn + lane]) * LOG2E_F);
    int K = 0;
    sts32_(stAddr0, A);

    unsigned bits = __shfl_sync(FULLMASK, __float_as_uint(A), 16);  // lane16 live
    int ef = (int)(bits >> 23);
    K += ef - 127;
    float s0 = __uint_as_float((unsigned)(254 - ef) << 23);
    float gcur = ex2f_(fb[1 * Tn + lane] * LOG2E_F) * s0;  // g*s for step 1

    // feats prefetch queue, 5 deep: at step l, fq0 = f[l+1]
    float fq0 = fb[2 * Tn + lane];
    float fq1 = fb[3 * Tn + lane];
    float fq2 = fb[4 * Tn + lane];
    float fq3 = fb[5 * Tn + lane];
    float fq4 = fb[6 * Tn + lane];
    __syncwarp();

#define CRF_STEP(SBASE, STADDR, L)                                             \
    do {                                                                       \
        ull v0, v1, v2, v3, v4, v5, v6, v7;                                    \
        ull u0, u1, u2, u3, u4, u5, u6, u7;                                    \
        lds128_(v0, u0, (SBASE) + 0);    /* chain head: issue all LDS first */ \
        lds128_(v1, u1, (SBASE) + 16);                                         \
        lds128_(v2, u2, (SBASE) + 32);                                         \
        lds128_(v3, u3, (SBASE) + 48);                                         \
        lds128_(v4, u4, (SBASE) + 64);                                         \
        lds128_(v5, u5, (SBASE) + 80);                                         \
        lds128_(v6, u6, (SBASE) + 96);                                         \
        lds128_(v7, u7, (SBASE) + 112);                                        \
        /* independent work in the LDS latency shadow */                       \
        float gexp = ex2f_(fq0 * LOG2E_F);                                     \
        fq0 = fq1; fq1 = fq2; fq2 = fq3; fq3 = fq4;                            \
        int lp = (L) + 6; lp = lp < (Ln - 1) ? lp : (Ln - 1);                  \
        fq4 = fb[lp * Tn + lane];                                              \
        /* 4-accumulator packed tree */                                        \
        ull a0 = mul2_(E2[0], v0);                                             \
        ull a1 = mul2_(E2[1], u0);                                             \
        ull a2 = mul2_(E2[2], v1);                                             \
        ull a3 = mul2_(E2[3], u1);                                             \
        a0 = fma2_(E2[4], v2, a0);                                             \
        a1 = fma2_(E2[5], u2, a1);                                             \
        a2 = fma2_(E2[6], v3, a2);                                             \
        a3 = fma2_(E2[7], u3, a3);                                             \
        a0 = fma2_(E2[8], v4, a0);                                             \
        a1 = fma2_(E2[9], u4, a1);                                             \
        a2 = fma2_(E2[10], v5, a2);                                            \
        a3 = fma2_(E2[11], u5, a3);                                            \
        a0 = fma2_(E2[12], v6, a0);                                            \
        a1 = fma2_(E2[13], u6, a1);                                            \
        a2 = fma2_(E2[14], v7, a2);                                            \
        a3 = fma2_(E2[15], u7, a3);                                            \
        ull s01 = add2_(a0, a1);                                               \
        ull s23 = add2_(a2, a3);                                               \
        ull st = add2_(s01, s23);                                              \
        float lo, hi;                                                          \
        unpack2_(st, lo, hi);                                                  \
        float Anew = (lo + hi) * gcur;                                         \
        sts32_((STADDR), Anew);          /* chain tail; next LDS reads this */ \
        unsigned bts = __shfl_sync(FULLMASK, __float_as_uint(Anew), 16);       \
        int e_ = (int)(bts >> 23);                                             \
        K += e_ - 127;                                                         \
        gcur = gexp * __uint_as_float((unsigned)(254 - e_) << 23);             \
    } while (0)

    int l = 1;
    for (; l + 1 < len; l += 2) {   // l stays odd: buffer parity fixed
        CRF_STEP(sb0, stAddr1, l);
        CRF_STEP(sb1, stAddr0, l + 1);
    }
    if (l < len) {
        CRF_STEP(sb0, stAddr1, l);
    }
    const int fbuf = (len - 1) & 1;
    __syncwarp();

    // ---- gold path score (after scan; feats now L2-hot) ----
    float gold = 0.0f;
    for (int ll = lane; ll < len; ll += 32) {
        int t = tb[ll];
        int prev = (ll == 0) ? T_START : tb[ll - 1];
        gold += fb[ll * Tn + t] + trans[prev * Tn + t];
    }
    #pragma unroll
    for (int o = 16; o; o >>= 1) gold += __shfl_xor_sync(FULLMASK, gold, o);
    gold += trans[tb[len - 1] * Tn + T_STOP];

    // ---- final: dot with E column STOP (owned by lane STOP) ----
    if (lane == T_STOP) {
        const longlong2* sv = reinterpret_cast<const longlong2*>(&sm_e[fbuf][0]);
        ull a0 = 0ull, a1 = 0ull;
        #pragma unroll
        for (int k2 = 0; k2 < 8; k2++) {
            longlong2 v = sv[k2];
            a0 = fma2_(E2[2 * k2], (ull)v.x, a0);
            a1 = fma2_(E2[2 * k2 + 1], (ull)v.y, a1);
        }
        float x0, x1, y0, y1;
        unpack2_(a0, x0, x1);
        unpack2_(a1, y0, y1);
        float dot = (x0 + x1) + (y0 + y1);
        float fwd = (lg2f_(dot) + (float)K) * LN2_F;
        g_res[b] = fwd - gold;
    }
    __syncwarp();

    // ---- deterministic last-block reduction (256 -> scalar) ----
    int last = 0;
    if (lane == 0) {
        __threadfence();
        last = (atomicAdd(&g_cnt, 1) == NBLK - 1) ? 1 : 0;
    }
    last = __shfl_sync(FULLMASK, last, 0);
    if (last) {
        __threadfence();
        float v = 0.0f;
        #pragma unroll
        for (int k = 0; k < Bn / 32; k++) v += g_res[lane + 32 * k];
        #pragma unroll
        for (int o = 16; o; o >>= 1) v += __shfl_xor_sync(FULLMASK, v, o);
        if (lane == 0) {
            out[0] = v;
            g_cnt = 0;  // reset for graph replay
        }
    }
}

extern "C" void kernel_launch(void* const* d_in, const int* in_sizes, int n_in,
                              void* d_out, int out_size) {
    const float* feats = (const float*)d_in[0];
    const void* mask = (const void*)d_in[1];
    const int* tags = (const int*)d_in[2];
    const float* trans = (const float*)d_in[3];

    crf_kernel<<<NBLK, 32>>>(feats, mask, tags, trans, (float*)d_out);
}

// round 6
// speedup vs baseline: 1.1496x; 1.1496x over previous
#include <cuda_runtime.h>
#include <cstdint>

// CRF NLL, linear-domain scaled forward. B=256, L=512, T=32 (START=30, STOP=31).
// WPB=2 warps(batches)/block -> 128 CTAs, <=1 CTA/SM, warps on SMSP0+SMSP1,
// nw=2/SM keeps LDS->LDS issue floor at 2.
// Per warp (thread j = tag j):
//   alpha'_j = g_j * s * sum_i E[i][j] * alpha_i
//   E = exp(trans) in registers (packed f32x2 column per thread),
//   g_j = exp(feats[l,j]) computed in the LDS latency shadow,
//   s = 2^{-k} exact rescale from exponent field of shfl'd alpha (off-chain).
// No per-step __syncwarp: converged warp, asm-pinned STS->LDS order (same-warp
// MIO wavefronts are processed in order). Gold path after the scan. Reduction fused.

static constexpr int Bn = 256;
static constexpr int Ln = 512;
static constexpr int Tn = 32;
static constexpr int T_START = 30;
static constexpr int T_STOP  = 31;
static constexpr int WPB = 2;
static constexpr int NBLK = Bn / WPB;     // 128

#define FULLMASK 0xffffffffu
#define LOG2E_F 1.4426950408889634f
#define LN2_F   0.6931471805599453f

typedef unsigned long long ull;

__device__ float g_res[Bn];
__device__ int g_cnt = 0;

__device__ __forceinline__ float ex2f_(float x) {
    float y; asm("ex2.approx.f32 %0, %1;" : "=f"(y) : "f"(x)); return y;
}
__device__ __forceinline__ float lg2f_(float x) {
    float y; asm("lg2.approx.f32 %0, %1;" : "=f"(y) : "f"(x)); return y;
}
__device__ __forceinline__ ull fma2_(ull a, ull b, ull c) {
    ull d; asm("fma.rn.f32x2 %0, %1, %2, %3;" : "=l"(d) : "l"(a), "l"(b), "l"(c));
    return d;
}
__device__ __forceinline__ ull mul2_(ull a, ull b) {
    ull d; asm("mul.rn.f32x2 %0, %1, %2;" : "=l"(d) : "l"(a), "l"(b));
    return d;
}
__device__ __forceinline__ ull add2_(ull a, ull b) {
    ull d; asm("add.rn.f32x2 %0, %1, %2;" : "=l"(d) : "l"(a), "l"(b));
    return d;
}
__device__ __forceinline__ ull pack2_(float lo, float hi) {
    ull d;
    asm("mov.b64 %0, {%1, %2};" : "=l"(d)
        : "r"(__float_as_uint(lo)), "r"(__float_as_uint(hi)));
    return d;
}
__device__ __forceinline__ void unpack2_(ull v, float& lo, float& hi) {
    unsigned a, b;
    asm("mov.b64 {%0, %1}, %2;" : "=r"(a), "=r"(b) : "l"(v));
    lo = __uint_as_float(a); hi = __uint_as_float(b);
}
// LDS.128 into two packed 64-bit regs; volatile pins order vs the STS.
__device__ __forceinline__ void lds128_(ull& a, ull& b, unsigned addr) {
    asm volatile("ld.shared.v2.b64 {%0, %1}, [%2];"
                 : "=l"(a), "=l"(b) : "r"(addr));
}
__device__ __forceinline__ void sts32_(unsigned addr, float v) {
    asm volatile("st.shared.b32 [%0], %1;" :: "r"(addr), "f"(v) : "memory");
}

__global__ void __launch_bounds__(WPB * 32, 1)
crf_kernel(const float* __restrict__ feats,
           const void* __restrict__ maskp,
           const int* __restrict__ tags,
           const float* __restrict__ trans,
           float* __restrict__ out) {
    __shared__ __align__(16) float sm_e[WPB][2][Tn];
    __shared__ float red[WPB];
    __shared__ int isLast;

    const int warp = threadIdx.x >> 5;
    const int lane = threadIdx.x & 31;
    const int b = blockIdx.x * WPB + warp;

    const float* __restrict__ fb = feats + (size_t)b * (Ln * Tn);
    const int* __restrict__ tb = tags + (size_t)b * Ln;

    const unsigned sb0 = (unsigned)__cvta_generic_to_shared(&sm_e[warp][0][0]);
    const unsigned sb1 = sb0 + Tn * 4;
    const unsigned stAddr0 = sb0 + lane * 4;
    const unsigned stAddr1 = sb1 + lane * 4;

    // ---- sequence length (mask = contiguous true-prefix; dtype detected) ----
    const unsigned w0 = ((const unsigned*)maskp)[0];  // mask[0,0] is true
    int cnt = 0;
    if (w0 == 1u) {                       // bool as int32
        const int* mb = (const int*)maskp + (size_t)b * Ln;
        #pragma unroll 4
        for (int l = lane; l < Ln; l += 32) cnt += (mb[l] != 0);
    } else if (w0 == 0x3F800000u) {       // bool as float32
        const float* mb = (const float*)maskp + (size_t)b * Ln;
        #pragma unroll 4
        for (int l = lane; l < Ln; l += 32) cnt += (mb[l] != 0.0f);
    } else {                              // bool as uint8
        const unsigned char* mb = (const unsigned char*)maskp + (size_t)b * Ln;
        #pragma unroll 4
        for (int l = lane; l < Ln; l += 32) cnt += (mb[l] != 0);
    }
    const int len = __reduce_add_sync(FULLMASK, cnt);

    // ---- E column for tag j = lane: E2[i] = {exp(trans[2i][j]), exp(trans[2i+1][j])} ----
    ull E2[Tn / 2];
    #pragma unroll
    for (int i = 0; i < Tn / 2; i++) {
        float e0 = ex2f_(trans[(2 * i) * Tn + lane] * LOG2E_F);
        float e1 = ex2f_(trans[(2 * i + 1) * Tn + lane] * LOG2E_F);
        E2[i] = pack2_(e0, e1);
    }

    // ---- init: alpha_j = exp(feats[0,j] + trans[START,j]), K = 0 ----
    float A = ex2f_((fb[lane] + trans[T_START * Tn + lane]) * LOG2E_F);
    int K = 0;
    sts32_(stAddr0, A);

    unsigned bits = __shfl_sync(FULLMASK, __float_as_uint(A), 16);  // lane16 live
    int ef = (int)(bits >> 23);
    K += ef - 127;
    float s0 = __uint_as_float((unsigned)(254 - ef) << 23);
    float gcur = ex2f_(fb[1 * Tn + lane] * LOG2E_F) * s0;  // g*s for step 1

    // feats prefetch queue, 4 deep: at step l, fq0 = f[l+1]
    float fq0 = fb[2 * Tn + lane];
    float fq1 = fb[3 * Tn + lane];
    float fq2 = fb[4 * Tn + lane];
    float fq3 = fb[5 * Tn + lane];
    __syncwarp();

#define CRF_STEP(SBASE, STADDR, L)                                             \
    do {                                                                       \
        ull v0, v1, v2, v3, v4, v5, v6, v7;                                    \
        ull u0, u1, u2, u3, u4, u5, u6, u7;                                    \
        lds128_(v0, u0, (SBASE) + 0);    /* chain head: issue all LDS first */ \
        lds128_(v1, u1, (SBASE) + 16);                                         \
        lds128_(v2, u2, (SBASE) + 32);                                         \
        lds128_(v3, u3, (SBASE) + 48);                                         \
        lds128_(v4, u4, (SBASE) + 64);                                         \
        lds128_(v5, u5, (SBASE) + 80);                                         \
        lds128_(v6, u6, (SBASE) + 96);                                         \
        lds128_(v7, u7, (SBASE) + 112);                                        \
        /* independent work in the LDS latency shadow */                       \
        float gexp = ex2f_(fq0 * LOG2E_F);                                     \
        fq0 = fq1; fq1 = fq2; fq2 = fq3;                                       \
        int lp = (L) + 5; lp = lp < (Ln - 1) ? lp : (Ln - 1);                  \
        fq3 = fb[lp * Tn + lane];                                              \
        /* 4-accumulator packed tree */                                        \
        ull a0 = mul2_(E2[0], v0);                                             \
        ull a1 = mul2_(E2[1], u0);                                             \
        ull a2 = mul2_(E2[2], v1);                                             \
        ull a3 = mul2_(E2[3], u1);                                             \
        a0 = fma2_(E2[4], v2, a0);                                             \
        a1 = fma2_(E2[5], u2, a1);                                             \
        a2 = fma2_(E2[6], v3, a2);                                             \
        a3 = fma2_(E2[7], u3, a3);                                             \
        a0 = fma2_(E2[8], v4, a0);                                             \
        a1 = fma2_(E2[9], u4, a1);                                             \
        a2 = fma2_(E2[10], v5, a2);                                            \
        a3 = fma2_(E2[11], u5, a3);                                            \
        a0 = fma2_(E2[12], v6, a0);                                            \
        a1 = fma2_(E2[13], u6, a1);                                            \
        a2 = fma2_(E2[14], v7, a2);                                            \
        a3 = fma2_(E2[15], u7, a3);                                            \
        ull s01 = add2_(a0, a1);                                               \
        ull s23 = add2_(a2, a3);                                               \
        ull st = add2_(s01, s23);                                              \
        float lo, hi;                                                          \
        unpack2_(st, lo, hi);                                                  \
        float Anew = (lo + hi) * gcur;                                         \
        sts32_((STADDR), Anew);          /* chain tail; next LDS reads this */ \
        unsigned bts = __shfl_sync(FULLMASK, __float_as_uint(Anew), 16);       \
        int e_ = (int)(bts >> 23);                                             \
        K += e_ - 127;                                                         \
        gcur = gexp * __uint_as_float((unsigned)(254 - e_) << 23);             \
    } while (0)

    int l = 1;
    for (; l + 1 < len; l += 2) {   // l stays odd: buffer parity fixed
        CRF_STEP(sb0, stAddr1, l);
        CRF_STEP(sb1, stAddr0, l + 1);
    }
    if (l < len) {
        CRF_STEP(sb0, stAddr1, l);
    }
    const int fbuf = (len - 1) & 1;
    __syncwarp();

    // ---- gold path score (after scan; feats now L2-hot) ----
    float gold = 0.0f;
    for (int ll = lane; ll < len; ll += 32) {
        int t = tb[ll];
        int prev = (ll == 0) ? T_START : tb[ll - 1];
        gold += fb[ll * Tn + t] + trans[prev * Tn + t];
    }
    #pragma unroll
    for (int o = 16; o; o >>= 1) gold += __shfl_xor_sync(FULLMASK, gold, o);
    gold += trans[tb[len - 1] * Tn + T_STOP];

    // ---- final: dot with E column STOP (owned by lane STOP) ----
    if (lane == T_STOP) {
        const float* sv = &sm_e[warp][fbuf][0];
        ull a0 = 0ull, a1 = 0ull;
        #pragma unroll
        for (int k2 = 0; k2 < 8; k2++) {
            ull vx = pack2_(sv[4 * k2 + 0], sv[4 * k2 + 1]);
            ull vy = pack2_(sv[4 * k2 + 2], sv[4 * k2 + 3]);
            a0 = fma2_(E2[2 * k2], vx, a0);
            a1 = fma2_(E2[2 * k2 + 1], vy, a1);
        }
        float x0, x1, y0, y1;
        unpack2_(a0, x0, x1);
        unpack2_(a1, y0, y1);
        float dot = (x0 + x1) + (y0 + y1);
        float fwd = (lg2f_(dot) + (float)K) * LN2_F;
        g_res[b] = fwd - gold;
    }

    // ---- deterministic last-block reduction (256 -> scalar) ----
    __syncthreads();
    if (threadIdx.x == 0) {
        __threadfence();
        isLast = (atomicAdd(&g_cnt, 1) == NBLK - 1) ? 1 : 0;
    }
    __syncthreads();
    if (isLast) {
        __threadfence();
        int t = threadIdx.x;  // 0..63
        float v = (g_res[t] + g_res[t + 64]) + (g_res[t + 128] + g_res[t + 192]);
        #pragma unroll
        for (int o = 16; o; o >>= 1) v += __shfl_xor_sync(FULLMASK, v, o);
        if ((t & 31) == 0) red[t >> 5] = v;
        __syncthreads();
        if (t == 0) {
            out[0] = red[0] + red[1];
            g_cnt = 0;  // reset for graph replay
        }
    }
}

extern "C" void kernel_launch(void* const* d_in, const int* in_sizes, int n_in,
                              void* d_out, int out_size) {
    const float* feats = (const float*)d_in[0];
    const void* mask = (const void*)d_in[1];
    const int* tags = (const int*)d_in[2];
    const float* trans = (const float*)d_in[3];

    crf_kernel<<<NBLK, WPB * 32>>>(feats, mask, tags, trans, (float*)d_out);
}